// round 4
// baseline (speedup 1.0000x reference)
#include <cuda_runtime.h>
#include <math.h>
#include <stdint.h>

#define NN 2048
#define TT 64
#define FF 16
#define HH 64
#define LL 16
#define KK 10
#define NKEYS (NN*LL)            // 32768
#define NSPLIT 16
#define KEYS_PER_KB (NKEYS/NSPLIT)   // 2048
#define TILE_KEYS 128
#define QTILE 128

// ---------------- scratch (static device memory; no allocation) ----------------
__device__ float g_xp[NN*TT*192];          // precomputed input gates (+b_ih)
__device__ float g_htail[NN*LL*HH];        // last-16 hidden states
__device__ float g_q[NN*HH];               // queries
__device__ float g_keysT[HH*NKEYS];        // projected keys, TRANSPOSED [h][key]
__device__ float g_pv[NN*NSPLIT*KK];       // partial top-k values
__device__ int   g_pi[NN*NSPLIT*KK];       // partial top-k indices

// ---------------- packed fp32x2 helpers ----------------
typedef unsigned long long u64t;
__device__ __forceinline__ void ffma2(u64t &d, u64t a, u64t b) {
    asm("fma.rn.f32x2 %0, %1, %2, %3;" : "=l"(d) : "l"(a), "l"(b), "l"(d));
}
__device__ __forceinline__ float f2sum(u64t v) {
    return __uint_as_float((uint32_t)v) + __uint_as_float((uint32_t)(v >> 32));
}
__device__ __forceinline__ u64t pack2(float a) {
    u64t r;
    asm("mov.b64 %0, {%1, %1};" : "=l"(r) : "f"(a));
    return r;
}
__device__ __forceinline__ float f2lo(u64t v) { return __uint_as_float((uint32_t)v); }
__device__ __forceinline__ float f2hi(u64t v) { return __uint_as_float((uint32_t)(v >> 32)); }

// ============================ K0: xp = x @ W_ih^T + b_ih ============================
__global__ void __launch_bounds__(192) xp_kernel(
    const float* __restrict__ x,
    const float* __restrict__ Wih, const float* __restrict__ bih)
{
    __shared__ float sW[192*16];
    __shared__ float sx[32*16];
    __shared__ float sb[192];
    const int tid = threadIdx.x;
    const int row0 = blockIdx.x * 32;

    for (int i = tid; i < 192*16; i += 192) sW[i] = Wih[i];
    for (int i = tid; i < 32*16; i += 192)  sx[i] = x[row0*16 + i];
    sb[tid] = bih[tid];
    __syncthreads();

    const int j = tid;
    u64t w2[8];
    #pragma unroll
    for (int q = 0; q < 8; ++q) w2[q] = *(const u64t*)&sW[j*16 + q*2];
    const float bj = sb[j];

    #pragma unroll 4
    for (int r = 0; r < 32; ++r) {
        u64t acc = 0;
        #pragma unroll
        for (int q = 0; q < 8; ++q)
            ffma2(acc, *(const u64t*)&sx[r*16 + q*2], w2[q]);
        g_xp[(row0 + r)*192 + j] = f2sum(acc) + bj;
    }
}

// ============================ K1: GRU recurrence (gh only) ============================
#define WS 66
#define GRU_SMEM_FLOATS (192*WS + 16*WS + 192)

__global__ void __launch_bounds__(256, 1) gru_kernel(const float* __restrict__ Whh,
                                                     const float* __restrict__ bhh)
{
    extern __shared__ float sm[];
    float* sWhh = sm;               // 192*66
    float* sh   = sWhh + 192*WS;    // 16*66
    float* sbhh = sh + 16*WS;       // 192

    const int tid = threadIdx.x;
    const int n0  = blockIdx.x * 16;

    for (int i = tid; i < 192*64; i += 256) { int j = i >> 6, k = i & 63; sWhh[j*WS + k] = Whh[i]; }
    if (tid < 192) sbhh[tid] = bhh[tid];
    for (int i = tid; i < 16*WS; i += 256) sh[i] = 0.0f;
    __syncthreads();

    const int jl = tid & 63;
    const int rb = tid >> 6;

    const float b_r = sbhh[jl];
    const float b_z = sbhh[64 + jl];
    const float b_n = sbhh[128 + jl];

    for (int t = 0; t < TT; ++t) {
        float xr[4], xz[4], xn[4];
        #pragma unroll
        for (int i = 0; i < 4; ++i) {
            const float* xpp = &g_xp[((n0 + rb*4 + i)*TT + t)*192];
            xr[i] = xpp[jl]; xz[i] = xpp[64 + jl]; xn[i] = xpp[128 + jl];
        }

        u64t acc2[4][3];
        #pragma unroll
        for (int i = 0; i < 4; ++i)
            #pragma unroll
            for (int u = 0; u < 3; ++u) acc2[i][u] = 0;

        #pragma unroll
        for (int kc = 0; kc < 64; kc += 4) {
            u64t wa[3], wb[3];
            #pragma unroll
            for (int u = 0; u < 3; ++u) {
                const float* wp = &sWhh[(jl + 64*u)*WS + kc];
                wa[u] = *(const u64t*)wp;
                wb[u] = *(const u64t*)(wp + 2);
            }
            #pragma unroll
            for (int i = 0; i < 4; ++i) {
                const float* hp = &sh[(rb*4 + i)*WS + kc];
                u64t ha = *(const u64t*)hp;
                u64t hb = *(const u64t*)(hp + 2);
                #pragma unroll
                for (int u = 0; u < 3; ++u) {
                    ffma2(acc2[i][u], ha, wa[u]);
                    ffma2(acc2[i][u], hb, wb[u]);
                }
            }
        }
        __syncthreads();

        #pragma unroll
        for (int i = 0; i < 4; ++i) {
            int r = rb*4 + i;
            float hr = f2sum(acc2[i][0]) + b_r;
            float hz = f2sum(acc2[i][1]) + b_z;
            float hn = f2sum(acc2[i][2]) + b_n;
            float rg = 1.0f / (1.0f + __expf(-(xr[i] + hr)));
            float zg = 1.0f / (1.0f + __expf(-(xz[i] + hz)));
            float targ = xn[i] + rg * hn;
            float e2 = __expf(2.0f * targ);
            float ng = 1.0f - 2.0f / (e2 + 1.0f);
            float ho = sh[r*WS + jl];
            float hnew = (1.0f - zg) * ng + zg * ho;
            sh[r*WS + jl] = hnew;
            if (t >= TT - LL)
                g_htail[((n0 + r)*LL + (t - (TT - LL)))*HH + jl] = hnew;
        }
        __syncthreads();
    }
}

// ============================ K2: q/k projections (keys written transposed) ============================
__global__ void __launch_bounds__(256) qk_kernel(const float* __restrict__ Wq,
                                                 const float* __restrict__ Wk)
{
    __shared__ float sWq[64*68];
    __shared__ float sWk[64*68];
    __shared__ float sht[16*68];
    const int tid = threadIdx.x;
    const int n   = blockIdx.x;

    for (int i = tid; i < 64*64; i += 256) { int j = i >> 6, k = i & 63; sWq[j*68+k] = Wq[i]; sWk[j*68+k] = Wk[i]; }
    for (int i = tid; i < 16*64; i += 256) { int l = i >> 6, k = i & 63; sht[l*68+k] = g_htail[(n*16 + l)*64 + k]; }
    __syncthreads();

    const int tx = tid & 15, l = tid >> 4;
    float acc[4] = {0.f, 0.f, 0.f, 0.f};
    #pragma unroll
    for (int k = 0; k < 64; k += 4) {
        float4 hv = *(const float4*)&sht[l*68 + k];
        #pragma unroll
        for (int u = 0; u < 4; ++u) {
            float4 wv = *(const float4*)&sWk[(tx + 16*u)*68 + k];
            acc[u] = fmaf(hv.x, wv.x, fmaf(hv.y, wv.y, fmaf(hv.z, wv.z, fmaf(hv.w, wv.w, acc[u]))));
        }
    }
    // transposed: g_keysT[h][key]
    #pragma unroll
    for (int u = 0; u < 4; ++u)
        g_keysT[(tx + 16*u)*NKEYS + n*16 + l] = acc[u];

    if (tid < 64) {
        float a = 0.f;
        #pragma unroll
        for (int k = 0; k < 64; k += 4) {
            float4 hv = *(const float4*)&sht[15*68 + k];
            float4 wv = *(const float4*)&sWq[tid*68 + k];
            a = fmaf(hv.x, wv.x, fmaf(hv.y, wv.y, fmaf(hv.z, wv.z, fmaf(hv.w, wv.w, a))));
        }
        g_q[n*64 + tid] = a;
    }
}

// ============================ K3: 8x8 col-pair FFMA2 GEMM + fused partial top-k ============================
#define WSQ 66     // q tile row stride (words)
#define WST 130    // transposed k tile row stride (words)
// smem floats: sq 128*66=8448, skt 64*130=8320, sv 1280, vmin 128, si 1280, slock 128
#define K3_SMEM_FLOATS (QTILE*WSQ + HH*WST + 1280 + 128 + 1280 + 128)
#define K3_SMEM_BYTES (K3_SMEM_FLOATS*4)

__device__ __forceinline__ void topk_insert(float* sv, int* si, volatile float* svmin,
                                            int* slock, int r, float val, int idx)
{
    bool done = false;
    while (!done) {
        if (atomicCAS(&slock[r], 0, 1) == 0) {
            float mn = sv[r*10]; int mp = 0;
            #pragma unroll
            for (int e = 1; e < 10; ++e) { float v = sv[r*10+e]; if (v < mn) { mn = v; mp = e; } }
            if (val > mn) {
                sv[r*10+mp] = val; si[r*10+mp] = idx;
                float nm = sv[r*10];
                #pragma unroll
                for (int e = 1; e < 10; ++e) { float v = sv[r*10+e]; if (v < nm) nm = v; }
                svmin[r] = nm;
            }
            __threadfence_block();
            atomicExch(&slock[r], 0);
            done = true;
        }
    }
}

__global__ void __launch_bounds__(256, 2) scores_topk_kernel()
{
    extern __shared__ float sm[];
    float* sq    = sm;                    // 128*66
    float* skt   = sq + QTILE*WSQ;        // 64*130 (transposed: [kc][col])
    float* sv    = skt + HH*WST;          // 128*10
    float* svminS= sv + 1280;             // 128
    int*   si    = (int*)(svminS + 128);  // 128*10
    int*   slock = si + 1280;             // 128

    const int tid = threadIdx.x;
    const int qb  = blockIdx.x;          // 0..15
    const int kb  = blockIdx.y;          // 0..15

    // load 128 q-rows (stride-66, u64 writes keep 8B alignment)
    for (int i = tid; i < QTILE*16; i += 256) {
        int r = i >> 4, c = (i & 15)*4;
        float4 v = *(const float4*)&g_q[(qb*QTILE + r)*HH + c];
        u64t* d = (u64t*)&sq[r*WSQ + c];
        d[0] = ((u64t*)&v)[0]; d[1] = ((u64t*)&v)[1];
    }
    for (int i = tid; i < 1280; i += 256) sv[i] = -INFINITY;
    if (tid < 128) { svminS[tid] = -INFINITY; slock[tid] = 0; }
    __syncthreads();

    const int tx = tid & 15, ty = tid >> 4;
    const int kbase0 = kb * KEYS_PER_KB;
    volatile float* vmin = svminS;

    const float* bq = &sq[ty*WSQ];       // row = ty + 16*i -> imm offset i*16*WSQ + kc
    const float* bk = &skt[2*tx];        // col-pair base -> imm offset kc*WST + 32*u

    for (int tt = 0; tt < KEYS_PER_KB / TILE_KEYS; ++tt) {
        const int kbase = kbase0 + tt*TILE_KEYS;

        // load k tile transposed: skt[h][col], coalesced from g_keysT
        for (int i = tid; i < HH*32; i += 256) {
            int h = i >> 5, c = (i & 31)*4;
            float4 v = *(const float4*)&g_keysT[h*NKEYS + kbase + c];
            u64t* d = (u64t*)&skt[h*WST + c];
            d[0] = ((u64t*)&v)[0]; d[1] = ((u64t*)&v)[1];
        }
        __syncthreads();

        // 8 rows x 4 col-pairs, accumulated as f32x2 (two adjacent columns per reg)
        u64t acc2[8][4];
        #pragma unroll
        for (int i = 0; i < 8; ++i)
            #pragma unroll
            for (int u = 0; u < 4; ++u) acc2[i][u] = 0;

        #pragma unroll 4
        for (int kc = 0; kc < 64; ++kc) {
            u64t b2[4];
            #pragma unroll
            for (int u = 0; u < 4; ++u) b2[u] = *(const u64t*)&bk[kc*WST + 32*u];
            #pragma unroll
            for (int i = 0; i < 8; ++i) {
                u64t a2 = pack2(bq[i*16*WSQ + kc]);
                #pragma unroll
                for (int u = 0; u < 4; ++u) ffma2(acc2[i][u], a2, b2[u]);
            }
        }

        // epilogue: unpack pairs directly (no cross-lane sum needed)
        #pragma unroll
        for (int i = 0; i < 8; ++i) {
            int r = ty + 16*i;
            int qrow = qb*QTILE + r;
            float thr = vmin[r];
            #pragma unroll
            for (int u = 0; u < 4; ++u) {
                int g0 = kbase + 2*tx + 32*u;
                float s0 = f2lo(acc2[i][u]);
                float s1 = f2hi(acc2[i][u]);
                if ((g0 >> 4) == qrow) { s0 = -1e9f; s1 = -1e9f; }
                if (s0 > thr) { topk_insert(sv, si, vmin, slock, r, s0, g0); thr = vmin[r]; }
                if (s1 > thr) { topk_insert(sv, si, vmin, slock, r, s1, g0 + 1); thr = vmin[r]; }
            }
        }
        __syncthreads();
    }

    if (tid < 128) {
        int qrow = qb*QTILE + tid;
        #pragma unroll
        for (int e = 0; e < 10; ++e) {
            g_pv[qrow*(NSPLIT*KK) + kb*KK + e] = sv[tid*10 + e];
            g_pi[qrow*(NSPLIT*KK) + kb*KK + e] = si[tid*10 + e];
        }
    }
}

// ============================ K4: merge + softmax + gather + MLP ============================
__global__ void __launch_bounds__(256) final_kernel(
    const float* __restrict__ x,
    const float* __restrict__ W1, const float* __restrict__ b1,
    const float* __restrict__ W2, const float* __restrict__ b2,
    float* __restrict__ out)
{
    const int warp = threadIdx.x >> 5, lane = threadIdx.x & 31;
    const int n = blockIdx.x * 8 + warp;

    float cv[5]; int ci[5];
    #pragma unroll
    for (int s = 0; s < 5; ++s) {
        int c = lane + 32*s;                  // 0..159
        cv[s] = g_pv[n*(NSPLIT*KK) + c];
        ci[s] = g_pi[n*(NSPLIT*KK) + c];
    }

    float topv[10]; int topi[10];
    #pragma unroll
    for (int it = 0; it < 10; ++it) {
        float bv = cv[0]; int bi = ci[0];
        #pragma unroll
        for (int s = 1; s < 5; ++s)
            if (cv[s] > bv || (cv[s] == bv && ci[s] < bi)) { bv = cv[s]; bi = ci[s]; }
        #pragma unroll
        for (int off = 16; off; off >>= 1) {
            float ov = __shfl_xor_sync(0xffffffffu, bv, off);
            int   oi = __shfl_xor_sync(0xffffffffu, bi, off);
            if (ov > bv || (ov == bv && oi < bi)) { bv = ov; bi = oi; }
        }
        topv[it] = bv; topi[it] = bi;
        #pragma unroll
        for (int s = 0; s < 5; ++s)
            if (ci[s] == bi) { cv[s] = -INFINITY; ci[s] = -2000 - s; }
    }

    float w[10]; float sumw = 0.0f;
    #pragma unroll
    for (int e = 0; e < 10; ++e) { w[e] = __expf(topv[e] - topv[0]); sumw += w[e]; }
    float inv = 1.0f / sumw;

    if (lane < 16) {
        float wf = 0.0f;
        #pragma unroll
        for (int e = 0; e < 10; ++e) {
            int m  = topi[e] >> 4;
            int ti = 48 + (topi[e] & 15);
            wf = fmaf(w[e] * inv, x[(m*TT + ti)*FF + lane], wf);
        }
        float hid = b1[lane];
        #pragma unroll
        for (int f = 0; f < 16; ++f)
            hid = fmaf(W1[lane*16 + f], __shfl_sync(0xffffu, wf, f), hid);
        hid = hid > 0.0f ? hid : 0.01f * hid;
        float val = hid * W2[lane];
        #pragma unroll
        for (int off = 8; off; off >>= 1)
            val += __shfl_xor_sync(0xffffu, val, off);
        if (lane == 0) out[n] = val + b2[0];
    }
}

// ============================ launch ============================
extern "C" void kernel_launch(void* const* d_in, const int* in_sizes, int n_in,
                              void* d_out, int out_size)
{
    const float* x   = (const float*)d_in[0];
    const float* Wih = (const float*)d_in[1];
    const float* Whh = (const float*)d_in[2];
    const float* bih = (const float*)d_in[3];
    const float* bhh = (const float*)d_in[4];
    const float* Wq  = (const float*)d_in[5];
    const float* Wk  = (const float*)d_in[6];
    const float* W1  = (const float*)d_in[7];
    const float* b1  = (const float*)d_in[8];
    const float* W2  = (const float*)d_in[9];
    const float* b2  = (const float*)d_in[10];
    float* out = (float*)d_out;

    const int gru_smem = GRU_SMEM_FLOATS * 4;
    cudaFuncSetAttribute(gru_kernel, cudaFuncAttributeMaxDynamicSharedMemorySize, gru_smem);
    cudaFuncSetAttribute(scores_topk_kernel, cudaFuncAttributeMaxDynamicSharedMemorySize, K3_SMEM_BYTES);

    xp_kernel<<<NN*TT/32, 192>>>(x, Wih, bih);
    gru_kernel<<<NN/16, 256, gru_smem>>>(Whh, bhh);
    qk_kernel<<<NN, 256>>>(Wq, Wk);
    dim3 g3(NN/QTILE, NSPLIT);
    scores_topk_kernel<<<g3, 256, K3_SMEM_BYTES>>>();
    final_kernel<<<NN/8, 256>>>(x, W1, b1, W2, b2, out);
}

// round 5
// speedup vs baseline: 4.5500x; 4.5500x over previous
#include <cuda_runtime.h>
#include <math.h>
#include <stdint.h>

#define NN 2048
#define TT 64
#define FF 16
#define HH 64
#define LL 16
#define KK 10
#define NKEYS (NN*LL)            // 32768
#define KBLOCKS 8
#define KEYS_PER_KB (NKEYS/KBLOCKS)  // 4096
#define TILE_KEYS 128

// ---------------- scratch (static device memory; no allocation) ----------------
__device__ float g_xp[NN*TT*192];          // precomputed input gates (+b_ih)
__device__ float g_htail[NN*LL*HH];        // last-16 hidden states
__device__ float g_q[NN*HH];               // queries
__device__ float g_keys[NN*LL*HH];         // projected keys, row-major [key][h]
__device__ float g_pv[NN*KBLOCKS*KK];      // partial top-k values
__device__ int   g_pi[NN*KBLOCKS*KK];      // partial top-k indices

// ---------------- packed fp32x2 helpers ----------------
typedef unsigned long long u64t;
__device__ __forceinline__ void ffma2(u64t &d, u64t a, u64t b) {
    asm("fma.rn.f32x2 %0, %1, %2, %3;" : "=l"(d) : "l"(a), "l"(b), "l"(d));
}
__device__ __forceinline__ float f2sum(u64t v) {
    return __uint_as_float((uint32_t)v) + __uint_as_float((uint32_t)(v >> 32));
}

// ============================ K0: xp = x @ W_ih^T + b_ih ============================
__global__ void __launch_bounds__(192) xp_kernel(
    const float* __restrict__ x,
    const float* __restrict__ Wih, const float* __restrict__ bih)
{
    __shared__ float sW[192*16];
    __shared__ float sx[32*16];
    __shared__ float sb[192];
    const int tid = threadIdx.x;
    const int row0 = blockIdx.x * 32;

    for (int i = tid; i < 192*16; i += 192) sW[i] = Wih[i];
    for (int i = tid; i < 32*16; i += 192)  sx[i] = x[row0*16 + i];
    sb[tid] = bih[tid];
    __syncthreads();

    const int j = tid;
    u64t w2[8];
    #pragma unroll
    for (int q = 0; q < 8; ++q) w2[q] = *(const u64t*)&sW[j*16 + q*2];
    const float bj = sb[j];

    #pragma unroll 4
    for (int r = 0; r < 32; ++r) {
        u64t acc = 0;
        #pragma unroll
        for (int q = 0; q < 8; ++q)
            ffma2(acc, *(const u64t*)&sx[r*16 + q*2], w2[q]);
        g_xp[(row0 + r)*192 + j] = f2sum(acc) + bj;
    }
}

// ============================ K1: GRU recurrence (gh only) ============================
#define WS 66
#define GRU_SMEM_FLOATS (192*WS + 16*WS + 192)

__global__ void __launch_bounds__(256, 1) gru_kernel(const float* __restrict__ Whh,
                                                     const float* __restrict__ bhh)
{
    extern __shared__ float sm[];
    float* sWhh = sm;               // 192*66
    float* sh   = sWhh + 192*WS;    // 16*66
    float* sbhh = sh + 16*WS;       // 192

    const int tid = threadIdx.x;
    const int n0  = blockIdx.x * 16;

    for (int i = tid; i < 192*64; i += 256) { int j = i >> 6, k = i & 63; sWhh[j*WS + k] = Whh[i]; }
    if (tid < 192) sbhh[tid] = bhh[tid];
    for (int i = tid; i < 16*WS; i += 256) sh[i] = 0.0f;
    __syncthreads();

    const int jl = tid & 63;
    const int rb = tid >> 6;

    const float b_r = sbhh[jl];
    const float b_z = sbhh[64 + jl];
    const float b_n = sbhh[128 + jl];

    for (int t = 0; t < TT; ++t) {
        float xr[4], xz[4], xn[4];
        #pragma unroll
        for (int i = 0; i < 4; ++i) {
            const float* xpp = &g_xp[((n0 + rb*4 + i)*TT + t)*192];
            xr[i] = xpp[jl]; xz[i] = xpp[64 + jl]; xn[i] = xpp[128 + jl];
        }

        u64t acc2[4][3];
        #pragma unroll
        for (int i = 0; i < 4; ++i)
            #pragma unroll
            for (int u = 0; u < 3; ++u) acc2[i][u] = 0;

        #pragma unroll
        for (int kc = 0; kc < 64; kc += 4) {
            u64t wa[3], wb[3];
            #pragma unroll
            for (int u = 0; u < 3; ++u) {
                const float* wp = &sWhh[(jl + 64*u)*WS + kc];
                wa[u] = *(const u64t*)wp;
                wb[u] = *(const u64t*)(wp + 2);
            }
            #pragma unroll
            for (int i = 0; i < 4; ++i) {
                const float* hp = &sh[(rb*4 + i)*WS + kc];
                u64t ha = *(const u64t*)hp;
                u64t hb = *(const u64t*)(hp + 2);
                #pragma unroll
                for (int u = 0; u < 3; ++u) {
                    ffma2(acc2[i][u], ha, wa[u]);
                    ffma2(acc2[i][u], hb, wb[u]);
                }
            }
        }
        __syncthreads();

        #pragma unroll
        for (int i = 0; i < 4; ++i) {
            int r = rb*4 + i;
            float hr = f2sum(acc2[i][0]) + b_r;
            float hz = f2sum(acc2[i][1]) + b_z;
            float hn = f2sum(acc2[i][2]) + b_n;
            float rg = 1.0f / (1.0f + __expf(-(xr[i] + hr)));
            float zg = 1.0f / (1.0f + __expf(-(xz[i] + hz)));
            float targ = xn[i] + rg * hn;
            float e2 = __expf(2.0f * targ);
            float ng = 1.0f - 2.0f / (e2 + 1.0f);
            float ho = sh[r*WS + jl];
            float hnew = (1.0f - zg) * ng + zg * ho;
            sh[r*WS + jl] = hnew;
            if (t >= TT - LL)
                g_htail[((n0 + r)*LL + (t - (TT - LL)))*HH + jl] = hnew;
        }
        __syncthreads();
    }
}

// ============================ K2: q/k projections (keys row-major) ============================
__global__ void __launch_bounds__(256) qk_kernel(const float* __restrict__ Wq,
                                                 const float* __restrict__ Wk)
{
    __shared__ float sWq[64*68];
    __shared__ float sWk[64*68];
    __shared__ float sht[16*68];
    const int tid = threadIdx.x;
    const int n   = blockIdx.x;

    for (int i = tid; i < 64*64; i += 256) { int j = i >> 6, k = i & 63; sWq[j*68+k] = Wq[i]; sWk[j*68+k] = Wk[i]; }
    for (int i = tid; i < 16*64; i += 256) { int l = i >> 6, k = i & 63; sht[l*68+k] = g_htail[(n*16 + l)*64 + k]; }
    __syncthreads();

    const int tx = tid & 15, l = tid >> 4;
    float acc[4] = {0.f, 0.f, 0.f, 0.f};
    #pragma unroll
    for (int k = 0; k < 64; k += 4) {
        float4 hv = *(const float4*)&sht[l*68 + k];
        #pragma unroll
        for (int u = 0; u < 4; ++u) {
            float4 wv = *(const float4*)&sWk[(tx + 16*u)*68 + k];
            acc[u] = fmaf(hv.x, wv.x, fmaf(hv.y, wv.y, fmaf(hv.z, wv.z, fmaf(hv.w, wv.w, acc[u]))));
        }
    }
    #pragma unroll
    for (int u = 0; u < 4; ++u)
        g_keys[(n*16 + l)*64 + tx + 16*u] = acc[u];

    if (tid < 64) {
        float a = 0.f;
        #pragma unroll
        for (int k = 0; k < 64; k += 4) {
            float4 hv = *(const float4*)&sht[15*68 + k];
            float4 wv = *(const float4*)&sWq[tid*68 + k];
            a = fmaf(hv.x, wv.x, fmaf(hv.y, wv.y, fmaf(hv.z, wv.z, fmaf(hv.w, wv.w, a))));
        }
        g_q[n*64 + tid] = a;
    }
}

// ============================ K3: 4x8 f32x2 GEMM (LDS.128 frags) + fused partial top-k ============================
#define WS2 68   // 272B row stride: 16B-aligned for LDS.128, conflict-free phases
// smem floats: sq 64*68 + sk 128*68 + sv 640 + vmin 64 + si 640 + slock 64
#define K3_SMEM_FLOATS (64*WS2 + 128*WS2 + 640 + 64 + 640 + 64)
#define K3_SMEM_BYTES (K3_SMEM_FLOATS*4)

__device__ __forceinline__ void topk_insert(float* sv, int* si, volatile float* svmin,
                                            int* slock, int r, float val, int idx)
{
    bool done = false;
    while (!done) {
        if (atomicCAS(&slock[r], 0, 1) == 0) {
            float mn = sv[r*10]; int mp = 0;
            #pragma unroll
            for (int e = 1; e < 10; ++e) { float v = sv[r*10+e]; if (v < mn) { mn = v; mp = e; } }
            if (val > mn) {
                sv[r*10+mp] = val; si[r*10+mp] = idx;
                float nm = sv[r*10];
                #pragma unroll
                for (int e = 1; e < 10; ++e) { float v = sv[r*10+e]; if (v < nm) nm = v; }
                svmin[r] = nm;
            }
            __threadfence_block();
            atomicExch(&slock[r], 0);
            done = true;
        }
    }
}

__global__ void __launch_bounds__(256, 2) scores_topk_kernel()
{
    extern __shared__ float sm[];
    float* sq    = sm;                   // 64*68
    float* sk    = sq + 64*WS2;          // 128*68
    float* sv    = sk + 128*WS2;         // 64*10
    float* svminS= sv + 640;             // 64
    int*   si    = (int*)(svminS + 64);  // 64*10
    int*   slock = si + 640;             // 64

    const int tid = threadIdx.x;
    const int qb  = blockIdx.x;        // 0..31
    const int kb  = blockIdx.y;        // 0..7

    for (int i = tid; i < 64*16; i += 256) {
        int r = i >> 4, c = (i & 15)*4;
        *(float4*)&sq[r*WS2 + c] = *(const float4*)&g_q[(qb*64 + r)*HH + c];
    }
    for (int i = tid; i < 640; i += 256) sv[i] = -INFINITY;
    if (tid < 64) { svminS[tid] = -INFINITY; slock[tid] = 0; }
    __syncthreads();

    const int tx = tid & 15, ty = tid >> 4;
    const int kbase0 = kb * KEYS_PER_KB;
    volatile float* vmin = svminS;

    const float* bq = &sq[ty*WS2];     // row  = ty + 16*i -> imm offset i*16*WS2 + kc
    const float* bk = &sk[tx*WS2];     // col  = tx + 16*u -> imm offset u*16*WS2 + kc

    for (int tt = 0; tt < KEYS_PER_KB / TILE_KEYS; ++tt) {
        const int kbase = kbase0 + tt*TILE_KEYS;

        for (int i = tid; i < 128*16; i += 256) {
            int kr = i >> 4, c = (i & 15)*4;
            *(float4*)&sk[kr*WS2 + c] = *(const float4*)&g_keys[(kbase + kr)*HH + c];
        }
        __syncthreads();

        u64t acc2[4][8];
        #pragma unroll
        for (int i = 0; i < 4; ++i)
            #pragma unroll
            for (int u = 0; u < 8; ++u) acc2[i][u] = 0;

        #pragma unroll 4
        for (int g = 0; g < 16; ++g) {
            const int kc = g*4;
            ulonglong2 kf[8];
            #pragma unroll
            for (int u = 0; u < 8; ++u)
                kf[u] = *(const ulonglong2*)&bk[u*16*WS2 + kc];     // LDS.128
            ulonglong2 qf[4];
            #pragma unroll
            for (int i = 0; i < 4; ++i)
                qf[i] = *(const ulonglong2*)&bq[i*16*WS2 + kc];     // LDS.128 (broadcast)
            #pragma unroll
            for (int i = 0; i < 4; ++i) {
                #pragma unroll
                for (int u = 0; u < 8; ++u) {
                    ffma2(acc2[i][u], qf[i].x, kf[u].x);
                    ffma2(acc2[i][u], qf[i].y, kf[u].y);
                }
            }
        }

        #pragma unroll
        for (int i = 0; i < 4; ++i) {
            int r = ty + 16*i;
            int qrow = qb*64 + r;
            float thr = vmin[r];
            #pragma unroll
            for (int u = 0; u < 8; ++u) {
                int g = kbase + tx + 16*u;
                float s = f2sum(acc2[i][u]);
                if ((g >> 4) == qrow) s = -1e9f;   // mask self (m == n)
                if (s > thr) {
                    topk_insert(sv, si, vmin, slock, r, s, g);
                    thr = vmin[r];
                }
            }
        }
        __syncthreads();
    }

    if (tid < 64) {
        int qrow = qb*64 + tid;
        #pragma unroll
        for (int e = 0; e < 10; ++e) {
            g_pv[qrow*80 + kb*10 + e] = sv[tid*10 + e];
            g_pi[qrow*80 + kb*10 + e] = si[tid*10 + e];
        }
    }
}

// ============================ K4: merge + softmax + gather + MLP ============================
__global__ void __launch_bounds__(256) final_kernel(
    const float* __restrict__ x,
    const float* __restrict__ W1, const float* __restrict__ b1,
    const float* __restrict__ W2, const float* __restrict__ b2,
    float* __restrict__ out)
{
    const int warp = threadIdx.x >> 5, lane = threadIdx.x & 31;
    const int n = blockIdx.x * 8 + warp;

    float cv[3]; int ci[3];
    #pragma unroll
    for (int s = 0; s < 3; ++s) {
        int c = lane + 32*s;
        if (c < 80) { cv[s] = g_pv[n*80 + c]; ci[s] = g_pi[n*80 + c]; }
        else        { cv[s] = -INFINITY;      ci[s] = -1000 - s; }
    }

    float topv[10]; int topi[10];
    #pragma unroll
    for (int it = 0; it < 10; ++it) {
        float bv = cv[0]; int bi = ci[0];
        if (cv[1] > bv || (cv[1] == bv && ci[1] < bi)) { bv = cv[1]; bi = ci[1]; }
        if (cv[2] > bv || (cv[2] == bv && ci[2] < bi)) { bv = cv[2]; bi = ci[2]; }
        #pragma unroll
        for (int off = 16; off; off >>= 1) {
            float ov = __shfl_xor_sync(0xffffffffu, bv, off);
            int   oi = __shfl_xor_sync(0xffffffffu, bi, off);
            if (ov > bv || (ov == bv && oi < bi)) { bv = ov; bi = oi; }
        }
        topv[it] = bv; topi[it] = bi;
        #pragma unroll
        for (int s = 0; s < 3; ++s)
            if (ci[s] == bi) { cv[s] = -INFINITY; ci[s] = -2000 - s; }
    }

    float w[10]; float sumw = 0.0f;
    #pragma unroll
    for (int e = 0; e < 10; ++e) { w[e] = __expf(topv[e] - topv[0]); sumw += w[e]; }
    float inv = 1.0f / sumw;

    if (lane < 16) {
        float wf = 0.0f;
        #pragma unroll
        for (int e = 0; e < 10; ++e) {
            int m  = topi[e] >> 4;
            int ti = 48 + (topi[e] & 15);
            wf = fmaf(w[e] * inv, x[(m*TT + ti)*FF + lane], wf);
        }
        float hid = b1[lane];
        #pragma unroll
        for (int f = 0; f < 16; ++f)
            hid = fmaf(W1[lane*16 + f], __shfl_sync(0xffffu, wf, f), hid);
        hid = hid > 0.0f ? hid : 0.01f * hid;
        float val = hid * W2[lane];
        #pragma unroll
        for (int off = 8; off; off >>= 1)
            val += __shfl_xor_sync(0xffffu, val, off);
        if (lane == 0) out[n] = val + b2[0];
    }
}

// ============================ launch ============================
extern "C" void kernel_launch(void* const* d_in, const int* in_sizes, int n_in,
                              void* d_out, int out_size)
{
    const float* x   = (const float*)d_in[0];
    const float* Wih = (const float*)d_in[1];
    const float* Whh = (const float*)d_in[2];
    const float* bih = (const float*)d_in[3];
    const float* bhh = (const float*)d_in[4];
    const float* Wq  = (const float*)d_in[5];
    const float* Wk  = (const float*)d_in[6];
    const float* W1  = (const float*)d_in[7];
    const float* b1  = (const float*)d_in[8];
    const float* W2  = (const float*)d_in[9];
    const float* b2  = (const float*)d_in[10];
    float* out = (float*)d_out;

    const int gru_smem = GRU_SMEM_FLOATS * 4;
    cudaFuncSetAttribute(gru_kernel, cudaFuncAttributeMaxDynamicSharedMemorySize, gru_smem);
    cudaFuncSetAttribute(scores_topk_kernel, cudaFuncAttributeMaxDynamicSharedMemorySize, K3_SMEM_BYTES);

    xp_kernel<<<NN*TT/32, 192>>>(x, Wih, bih);
    gru_kernel<<<NN/16, 256, gru_smem>>>(Whh, bhh);
    qk_kernel<<<NN, 256>>>(Wq, Wk);
    dim3 g3(NN/64, KBLOCKS);
    scores_topk_kernel<<<g3, 256, K3_SMEM_BYTES>>>();
    final_kernel<<<NN/8, 256>>>(x, W1, b1, W2, b2, out);
}